// round 2
// baseline (speedup 1.0000x reference)
#include <cuda_runtime.h>

// ---------------------------------------------------------------------------
// Causal spectral filter: out = irfft(rfft(x,16384) * spec)[..., :8192, :]
// spec derived from linear-interp of coeffs + Hilbert (analytic) window.
// B=8, N=8192, D=512, FFT=16384 (real) via 8192-pt complex Stockham FFT.
// ---------------------------------------------------------------------------

#define PHI(i) ((i) ^ (((i) >> 4) & 15))   // smem bank swizzle (bijective per 8192)

static __device__ float  g_xt[8u * 512u * 8192u];   // x transposed (B,D,N)
static __device__ float  g_yt[8u * 512u * 8192u];   // y transposed (B,D,N)
static __device__ float2 g_spec[512u * 8200u];      // per-channel spectrum, stride 8200
static __device__ float2 g_tw[8192];                // e^{-2pi i j/8192}

__device__ __forceinline__ float2 cadd(float2 a, float2 b) { return make_float2(a.x + b.x, a.y + b.y); }
__device__ __forceinline__ float2 csub(float2 a, float2 b) { return make_float2(a.x - b.x, a.y - b.y); }
__device__ __forceinline__ float2 cmul(float2 a, float2 b) {
    return make_float2(fmaf(a.x, b.x, -a.y * b.y), fmaf(a.x, b.y, a.y * b.x));
}
template <int S>
__device__ __forceinline__ float2 crot(float2 z) {   // multiply by S*i
    return (S < 0) ? make_float2(z.y, -z.x) : make_float2(-z.y, z.x);
}

// e^{-2pi i k/16384} for 0<=k<8192, from the 8192-table (+ one const mul for odd k)
__device__ __forceinline__ float2 tw2_of(const float2* tws, int k) {
    float2 h = tws[PHI(k >> 1)];
    if (k & 1) {
        const float2 h1 = make_float2(0.99999992646571789f, -3.8349518757139556e-4f); // e^{-i pi/8192}
        h = cmul(h, h1);
    }
    return h;
}

// 8192-point complex Stockham FFT in shared memory (4 x radix-8 + 1 x radix-2).
// SGN = -1: forward (e^{-2pi i jk/N}); SGN = +1: inverse, UNNORMALIZED.
// 512 threads. cur/alt are 8192-entry float2 smem buffers; tws is the table.
template <int SGN>
__device__ void fft8192(float2*& cur, float2*& alt, const float2* tws) {
    const int tid = threadIdx.x;
    const float C0 = 0.70710678118654752f;
    const float2 w81 = make_float2(C0, SGN * C0);
    const float2 w83 = make_float2(-C0, SGN * C0);
#pragma unroll
    for (int st = 0; st < 4; st++) {
        const int LS = 3 * st;
        __syncthreads();
#pragma unroll
        for (int half = 0; half < 2; half++) {
            int t = tid + (half << 9);
            int q = t & ((1 << LS) - 1);
            int ps = t - q;                       // p * s
            float2 a0 = cur[PHI(t)],        a1 = cur[PHI(t + 1024)];
            float2 a2 = cur[PHI(t + 2048)], a3 = cur[PHI(t + 3072)];
            float2 a4 = cur[PHI(t + 4096)], a5 = cur[PHI(t + 5120)];
            float2 a6 = cur[PHI(t + 6144)], a7 = cur[PHI(t + 7168)];
            float2 t0 = cadd(a0, a4), t4 = csub(a0, a4);
            float2 t1 = cadd(a1, a5), t5 = csub(a1, a5);
            float2 t2 = cadd(a2, a6), t6 = csub(a2, a6);
            float2 t3 = cadd(a3, a7), t7 = csub(a3, a7);
            float2 E0 = cadd(t0, t2), E2 = csub(t0, t2);
            float2 r6 = crot<SGN>(t6);
            float2 E1 = cadd(t4, r6), E3 = csub(t4, r6);
            float2 O0 = cadd(t1, t3), O2 = csub(t1, t3);
            float2 r7 = crot<SGN>(t7);
            float2 O1 = cadd(t5, r7), O3 = csub(t5, r7);
            float2 m1 = cmul(O1, w81);
            float2 m2 = crot<SGN>(O2);
            float2 m3 = cmul(O3, w83);
            float2 c0 = cadd(E0, O0), c4 = csub(E0, O0);
            float2 c1 = cadd(E1, m1), c5 = csub(E1, m1);
            float2 c2 = cadd(E2, m2), c6 = csub(E2, m2);
            float2 c3 = cadd(E3, m3), c7 = csub(E3, m3);
            int wb = (ps << 3) + q;
            alt[PHI(wb)] = c0;
            float2 cc[7] = {c1, c2, c3, c4, c5, c6, c7};
#pragma unroll
            for (int r = 1; r <= 7; r++) {
                float2 w = tws[PHI(ps * r)];
                if (SGN > 0) w.y = -w.y;
                alt[PHI(wb + (r << LS))] = cmul(cc[r - 1], w);
            }
        }
        float2* tmp = cur; cur = alt; alt = tmp;
    }
    __syncthreads();
#pragma unroll
    for (int it = 0; it < 8; it++) {
        int t = tid + (it << 9);
        float2 a = cur[PHI(t)], b = cur[PHI(t + 4096)];
        alt[PHI(t)] = cadd(a, b);
        alt[PHI(t + 4096)] = csub(a, b);
    }
    { float2* tmp = cur; cur = alt; alt = tmp; }
    __syncthreads();
}

// ---------------------------------------------------------------------------

__global__ void k_tw() {
    int j = blockIdx.x * blockDim.x + threadIdx.x;
    if (j < 8192) {
        double a = -2.0 * 3.14159265358979323846264338327950288 * (double)j / 8192.0;
        g_tw[j] = make_float2((float)cos(a), (float)sin(a));
    }
}

__global__ void k_tin(const float* __restrict__ x) {
    __shared__ float tile[32][33];
    int b = blockIdx.z;
    int d0 = blockIdx.x << 5, n0 = blockIdx.y << 5;
    int tx = threadIdx.x, ty = threadIdx.y;
    const float* xb = x + (size_t)b * 8192u * 512u;
#pragma unroll
    for (int i = ty; i < 32; i += 8)
        tile[i][tx] = xb[(size_t)(n0 + i) * 512u + d0 + tx];
    __syncthreads();
    float* xt = g_xt + (size_t)b * 512u * 8192u;
#pragma unroll
    for (int i = ty; i < 32; i += 8)
        xt[(size_t)(d0 + i) * 8192u + n0 + tx] = tile[tx][i];
}

__global__ void k_tout(float* __restrict__ out) {
    __shared__ float tile[32][33];
    int b = blockIdx.z;
    int d0 = blockIdx.x << 5, n0 = blockIdx.y << 5;
    int tx = threadIdx.x, ty = threadIdx.y;
    const float* yt = g_yt + (size_t)b * 512u * 8192u;
#pragma unroll
    for (int i = ty; i < 32; i += 8)
        tile[i][tx] = yt[(size_t)(d0 + i) * 8192u + n0 + tx];
    __syncthreads();
#pragma unroll
    for (int i = ty; i < 32; i += 8)
        out[((size_t)b * 8192u + n0 + i) * 512u + d0 + tx] = tile[tx][i];
}

// Per-channel: interp coeffs -> a[k] (real spectrum) -> irfft -> analytic
// window -> rfft -> g_spec[d][0..8192]
__global__ void __launch_bounds__(512) k_filter(const float* __restrict__ coeffs,
                                                const float* __restrict__ dc) {
    extern __shared__ float2 sm[];
    float2* tws = sm;            // 8192
    float2* A   = sm + 8192;     // 8192
    float2* Bb  = sm + 16384;    // 8192
    float*  cf  = (float*)(sm + 24576);   // 512 floats
    int d = blockIdx.x;
    int tid = threadIdx.x;
    for (int j = tid; j < 8192; j += 512) tws[PHI(j)] = g_tw[j];
    cf[tid] = coeffs[d * 512 + tid];
    float dcv = dc[d];
    __syncthreads();

    auto interp = [&](int k) -> float {
        if (k == 0) return dcv;
        float src = ((float)k - 0.5f) * 0.0625f - 0.5f;   // (i+0.5)/16 - 0.5, i=k-1
        src = fminf(fmaxf(src, 0.0f), 511.0f);
        int lo = (int)src;
        int hi = min(lo + 1, 511);
        float w = src - (float)lo;
        float clo = cf[lo];
        return fmaf(cf[hi] - clo, w, clo);
    };

    // Build Z for inverse-real-FFT of the real spectrum a[0..8192]
    for (int k = tid; k < 8192; k += 512) {
        float ak  = interp(k);
        float akk = interp(8192 - k);
        float fe = 0.5f * (ak + akk);
        float g  = 0.5f * (ak - akk);
        float2 t2 = tw2_of(tws, k);          // e^{-2pi i k/16384}
        // Z = fe + i * conj(t2)*g  =>  (fe + t2.y*g, t2.x*g)
        A[PHI(k)] = make_float2(fmaf(t2.y, g, fe), t2.x * g);
    }
    float2 *cur = A, *alt = Bb;
    fft8192<1>(cur, alt, tws);               // inverse (unnormalized)

    // analytic window (x2 middle), fold 1/8192 normalization; repack for rfft
    const float inv = 1.0f / 8192.0f;
    for (int j = tid; j < 8192; j += 512) {
        float2 z = cur[PHI(j)];
        float sx, sy;
        if (j == 0)         { sx = inv;        sy = 2.0f * inv; }
        else if (j < 4096)  { sx = 2.0f * inv; sy = 2.0f * inv; }
        else if (j == 4096) { sx = inv;        sy = 0.0f; }
        else                { sx = 0.0f;       sy = 0.0f; }
        cur[PHI(j)] = make_float2(z.x * sx, z.y * sy);
    }
    fft8192<-1>(cur, alt, tws);              // forward

    float2* sp = g_spec + (size_t)d * 8200u;
    for (int k = tid + 1; k <= 4095; k += 512) {
        float2 P = cur[PHI(k)], Q = cur[PHI(8192 - k)];
        float2 Fe = make_float2(0.5f * (P.x + Q.x), 0.5f * (P.y - Q.y));
        float2 Dd = make_float2(P.x - Q.x, P.y + Q.y);
        float2 Fo = make_float2(0.5f * Dd.y, -0.5f * Dd.x);
        float2 t2 = tw2_of(tws, k);
        float2 Xk = cadd(Fe, cmul(t2, Fo));
        float2 nt = make_float2(-t2.x, t2.y);                 // -conj(t2)
        float2 Xkk = cadd(make_float2(Fe.x, -Fe.y), cmul(nt, make_float2(Fo.x, -Fo.y)));
        sp[k] = Xk;
        sp[8192 - k] = Xkk;
    }
    if (tid == 0) {
        float2 Z0 = cur[PHI(0)];
        sp[0]    = make_float2(Z0.x + Z0.y, 0.0f);
        sp[8192] = make_float2(Z0.x - Z0.y, 0.0f);
        float2 Z4 = cur[PHI(4096)];
        sp[4096] = make_float2(Z4.x, -Z4.y);
    }
}

// Per (b,d): rfft(x row) * spec -> irfft -> first 8192 samples
__global__ void __launch_bounds__(512) k_conv() {
    extern __shared__ float2 sm[];
    float2* tws = sm;
    float2* A   = sm + 8192;
    float2* Bb  = sm + 16384;
    int bid = blockIdx.x;
    int d = bid & 511;
    int b = bid >> 9;
    int tid = threadIdx.x;
    for (int j = tid; j < 8192; j += 512) tws[PHI(j)] = g_tw[j];
    const float2* xr = (const float2*)(g_xt + ((size_t)(b * 512 + d) << 13));
    for (int j = tid; j < 4096; j += 512) A[PHI(j)] = xr[j];
    for (int j = 4096 + tid; j < 8192; j += 512) A[PHI(j)] = make_float2(0.f, 0.f);
    float2 *cur = A, *alt = Bb;
    fft8192<-1>(cur, alt, tws);              // forward

    const float2* sp = g_spec + (size_t)d * 8200u;
    for (int k = tid + 1; k <= 4095; k += 512) {
        int kk = 8192 - k;
        float2 P = cur[PHI(k)], Q = cur[PHI(kk)];
        float2 Fe = make_float2(0.5f * (P.x + Q.x), 0.5f * (P.y - Q.y));
        float2 Dd = make_float2(P.x - Q.x, P.y + Q.y);
        float2 Fo = make_float2(0.5f * Dd.y, -0.5f * Dd.x);
        float2 t2 = tw2_of(tws, k);
        float2 Xk = cadd(Fe, cmul(t2, Fo));
        float2 nt = make_float2(-t2.x, t2.y);
        float2 Xkk = cadd(make_float2(Fe.x, -Fe.y), cmul(nt, make_float2(Fo.x, -Fo.y)));
        float2 Yk  = cmul(Xk,  sp[k]);
        float2 Ykk = cmul(Xkk, sp[kk]);
        // inverse real-FFT pre-pass
        float2 Fe2 = make_float2(0.5f * (Yk.x + Ykk.x), 0.5f * (Yk.y - Ykk.y));
        float2 hd  = make_float2(0.5f * (Yk.x - Ykk.x), 0.5f * (Yk.y + Ykk.y));
        float2 ct2 = make_float2(t2.x, -t2.y);               // e^{+2pi i k/16384}
        float2 Fo2 = cmul(ct2, hd);
        cur[PHI(k)]  = make_float2(Fe2.x - Fo2.y,  Fe2.y + Fo2.x);
        cur[PHI(kk)] = make_float2(Fe2.x + Fo2.y, -Fe2.y + Fo2.x);
    }
    if (tid == 0) {
        float2 Z0 = cur[PHI(0)];
        float X0 = Z0.x + Z0.y;
        float XN = Z0.x - Z0.y;
        float Y0 = X0 * sp[0].x;
        float YN = XN * sp[8192].x;
        cur[PHI(0)] = make_float2(0.5f * (Y0 + YN), 0.5f * (Y0 - YN));
        float2 Z4 = cur[PHI(4096)];
        float2 X4 = make_float2(Z4.x, -Z4.y);
        float2 Y4 = cmul(X4, sp[4096]);
        cur[PHI(4096)] = make_float2(Y4.x, -Y4.y);
    }
    fft8192<1>(cur, alt, tws);               // inverse (unnormalized)

    const float inv = 1.0f / 8192.0f;
    float2* yr = (float2*)(g_yt + ((size_t)(b * 512 + d) << 13));
    for (int j = tid; j < 4096; j += 512) {
        float2 w = cur[PHI(j)];
        yr[j] = make_float2(w.x * inv, w.y * inv);
    }
}

// ---------------------------------------------------------------------------

extern "C" void kernel_launch(void* const* d_in, const int* in_sizes, int n_in,
                              void* d_out, int out_size) {
    const float* x      = (const float*)d_in[0];
    const float* coeffs = (const float*)d_in[1];
    const float* dc     = (const float*)d_in[2];
    float* out = (float*)d_out;

    size_t smem_c = 24576u * sizeof(float2);               // 196608
    size_t smem_f = smem_c + 512u * sizeof(float);         // 198656
    cudaFuncSetAttribute(k_filter, cudaFuncAttributeMaxDynamicSharedMemorySize, (int)smem_f);
    cudaFuncSetAttribute(k_conv,   cudaFuncAttributeMaxDynamicSharedMemorySize, (int)smem_c);

    k_tw<<<16, 512>>>();
    k_tin<<<dim3(16, 256, 8), dim3(32, 8)>>>(x);
    k_filter<<<512, 512, smem_f>>>(coeffs, dc);
    k_conv<<<4096, 512, smem_c>>>();
    k_tout<<<dim3(16, 256, 8), dim3(32, 8)>>>(out);
}

// round 3
// speedup vs baseline: 1.2524x; 1.2524x over previous
#include <cuda_runtime.h>

// ---------------------------------------------------------------------------
// Causal spectral filter: out = irfft(rfft(x,16384) * spec)[..., :8192, :]
// In-place mixed-radix [8,8,8,8,2] FFT (8192-pt complex), 2 blocks/SM.
// Forward: DIF, natural in -> digit-reversed out. Inverse: reversed stages,
// digit-reversed in -> natural out. Pointwise ops run in digit-rev domain.
// ---------------------------------------------------------------------------

#define IDX(i) ((i) + ((i) >> 4))     // smem pad: bank-conflict-free all stages

static __device__ float  g_xt[8u * 512u * 8192u];   // x transposed (B,D,N)
static __device__ float  g_yt[8u * 512u * 8192u];   // y transposed (B,D,N)
static __device__ float2 g_spec[512u * 8200u];      // per-channel spectrum (natural k)
static __device__ float2 g_tw[1024];                // W_8192^c, c<1024

__device__ __forceinline__ float2 cadd(float2 a, float2 b) { return make_float2(a.x + b.x, a.y + b.y); }
__device__ __forceinline__ float2 csub(float2 a, float2 b) { return make_float2(a.x - b.x, a.y - b.y); }
__device__ __forceinline__ float2 cmul(float2 a, float2 b) {
    return make_float2(fmaf(a.x, b.x, -a.y * b.y), fmaf(a.x, b.y, a.y * b.x));
}
template <int S>
__device__ __forceinline__ float2 crot(float2 z) {   // multiply by S*i
    return (S < 0) ? make_float2(z.y, -z.x) : make_float2(-z.y, z.x);
}

// digit-reverse for radices [8,8,8,8,2]: pos of coefficient k after fwd FFT
__device__ __forceinline__ int drev(int k) {
    return ((k & 7) << 10) | (((k >> 3) & 7) << 7) | (((k >> 6) & 7) << 4)
         | (((k >> 9) & 7) << 1) | ((k >> 12) & 1);
}

// W_16384^k for 0<=k<8192 from the 1024-entry table (2-3 cmuls)
__device__ __forceinline__ float2 tw16384(const float2* T, int k) {
    int a = k >> 1;
    float2 w = T[a & 1023];
    int u = (a >> 10) & 3;
    const float S2 = 0.70710678118654752f;
    if (u & 2) w = make_float2(w.y, -w.x);                       // * W_8^2 = -i
    if (u & 1) w = cmul(w, make_float2(S2, -S2));                // * W_8^1
    if (k & 1) w = cmul(w, make_float2(0.99999992646571789f, -3.8349518757139556e-4f));
    return w;
}

template <int SGN>
__device__ __forceinline__ void bfly8(float2& a0, float2& a1, float2& a2, float2& a3,
                                      float2& a4, float2& a5, float2& a6, float2& a7) {
    const float C0 = 0.70710678118654752f;
    const float2 w81 = make_float2(C0, SGN * C0);
    const float2 w83 = make_float2(-C0, SGN * C0);
    float2 t0 = cadd(a0, a4), t4 = csub(a0, a4);
    float2 t1 = cadd(a1, a5), t5 = csub(a1, a5);
    float2 t2 = cadd(a2, a6), t6 = csub(a2, a6);
    float2 t3 = cadd(a3, a7), t7 = csub(a3, a7);
    float2 E0 = cadd(t0, t2), E2 = csub(t0, t2);
    float2 r6 = crot<SGN>(t6);
    float2 E1 = cadd(t4, r6), E3 = csub(t4, r6);
    float2 O0 = cadd(t1, t3), O2 = csub(t1, t3);
    float2 r7 = crot<SGN>(t7);
    float2 O1 = cadd(t5, r7), O3 = csub(t5, r7);
    float2 m1 = cmul(O1, w81);
    float2 m2 = crot<SGN>(O2);
    float2 m3 = cmul(O3, w83);
    a0 = cadd(E0, O0); a4 = csub(E0, O0);
    a1 = cadd(E1, m1); a5 = csub(E1, m1);
    a2 = cadd(E2, m2); a6 = csub(E2, m2);
    a3 = cadd(E3, m3); a7 = csub(E3, m3);
}

// forward DIF radix-8 stage, span = 8*sub, sub = 1<<L2S. twiddle-after.
template <int L2S>
__device__ __forceinline__ void fwd_r8(float2* buf, const float2* T) {
    const int tid = threadIdx.x;
    const int sub = 1 << L2S;
#pragma unroll
    for (int h = 0; h < 2; h++) {
        int b = tid + (h << 9);
        int j = b & (sub - 1);
        int base = ((b >> L2S) << (L2S + 3)) + j;
        float2 a0 = buf[IDX(base)];
        float2 a1 = buf[IDX(base + sub)];
        float2 a2 = buf[IDX(base + 2 * sub)];
        float2 a3 = buf[IDX(base + 3 * sub)];
        float2 a4 = buf[IDX(base + 4 * sub)];
        float2 a5 = buf[IDX(base + 5 * sub)];
        float2 a6 = buf[IDX(base + 6 * sub)];
        float2 a7 = buf[IDX(base + 7 * sub)];
        bfly8<-1>(a0, a1, a2, a3, a4, a5, a6, a7);
        float2 w1 = T[j << (10 - L2S)];
        float2 w = w1;
        buf[IDX(base)] = a0;
        buf[IDX(base + sub)] = cmul(a1, w);      w = cmul(w, w1);
        buf[IDX(base + 2 * sub)] = cmul(a2, w);  w = cmul(w, w1);
        buf[IDX(base + 3 * sub)] = cmul(a3, w);  w = cmul(w, w1);
        buf[IDX(base + 4 * sub)] = cmul(a4, w);  w = cmul(w, w1);
        buf[IDX(base + 5 * sub)] = cmul(a5, w);  w = cmul(w, w1);
        buf[IDX(base + 6 * sub)] = cmul(a6, w);  w = cmul(w, w1);
        buf[IDX(base + 7 * sub)] = cmul(a7, w);
    }
}

// inverse (DIT-style) radix-8 stage: conj twiddle-before, conj DFT.
template <int L2S>
__device__ __forceinline__ void inv_r8(float2* buf, const float2* T) {
    const int tid = threadIdx.x;
    const int sub = 1 << L2S;
#pragma unroll
    for (int h = 0; h < 2; h++) {
        int b = tid + (h << 9);
        int j = b & (sub - 1);
        int base = ((b >> L2S) << (L2S + 3)) + j;
        float2 a0 = buf[IDX(base)];
        float2 a1 = buf[IDX(base + sub)];
        float2 a2 = buf[IDX(base + 2 * sub)];
        float2 a3 = buf[IDX(base + 3 * sub)];
        float2 a4 = buf[IDX(base + 4 * sub)];
        float2 a5 = buf[IDX(base + 5 * sub)];
        float2 a6 = buf[IDX(base + 6 * sub)];
        float2 a7 = buf[IDX(base + 7 * sub)];
        float2 w1 = T[j << (10 - L2S)];
        w1.y = -w1.y;
        float2 w = w1;
        a1 = cmul(a1, w);  w = cmul(w, w1);
        a2 = cmul(a2, w);  w = cmul(w, w1);
        a3 = cmul(a3, w);  w = cmul(w, w1);
        a4 = cmul(a4, w);  w = cmul(w, w1);
        a5 = cmul(a5, w);  w = cmul(w, w1);
        a6 = cmul(a6, w);  w = cmul(w, w1);
        a7 = cmul(a7, w);
        bfly8<1>(a0, a1, a2, a3, a4, a5, a6, a7);
        buf[IDX(base)] = a0;
        buf[IDX(base + sub)] = a1;
        buf[IDX(base + 2 * sub)] = a2;
        buf[IDX(base + 3 * sub)] = a3;
        buf[IDX(base + 4 * sub)] = a4;
        buf[IDX(base + 5 * sub)] = a5;
        buf[IDX(base + 6 * sub)] = a6;
        buf[IDX(base + 7 * sub)] = a7;
    }
}

__device__ __forceinline__ void r2_pass(float2* buf) {
    const int tid = threadIdx.x;
#pragma unroll
    for (int h = 0; h < 8; h++) {
        int b = tid + (h << 9);
        float2 a = buf[IDX(2 * b)], c = buf[IDX(2 * b + 1)];
        buf[IDX(2 * b)] = cadd(a, c);
        buf[IDX(2 * b + 1)] = csub(a, c);
    }
}

__device__ __forceinline__ void fft_fwd(float2* buf, const float2* T) {
    __syncthreads();
    fwd_r8<10>(buf, T); __syncthreads();
    fwd_r8<7>(buf, T);  __syncthreads();
    fwd_r8<4>(buf, T);  __syncthreads();
    fwd_r8<1>(buf, T);  __syncthreads();
    r2_pass(buf);       __syncthreads();
}

__device__ __forceinline__ void fft_inv(float2* buf, const float2* T) {
    __syncthreads();
    r2_pass(buf);       __syncthreads();
    inv_r8<1>(buf, T);  __syncthreads();
    inv_r8<4>(buf, T);  __syncthreads();
    inv_r8<7>(buf, T);  __syncthreads();
    inv_r8<10>(buf, T); __syncthreads();
}

// ---------------------------------------------------------------------------

__global__ void k_tw() {
    int j = blockIdx.x * blockDim.x + threadIdx.x;
    if (j < 1024) {
        double a = -2.0 * 3.14159265358979323846264338327950288 * (double)j / 8192.0;
        g_tw[j] = make_float2((float)cos(a), (float)sin(a));
    }
}

__global__ void k_tin(const float* __restrict__ x) {
    __shared__ float tile[32][33];
    int b = blockIdx.z;
    int d0 = blockIdx.x << 5, n0 = blockIdx.y << 5;
    int tx = threadIdx.x, ty = threadIdx.y;
    const float* xb = x + (size_t)b * 8192u * 512u;
#pragma unroll
    for (int i = ty; i < 32; i += 8)
        tile[i][tx] = xb[(size_t)(n0 + i) * 512u + d0 + tx];
    __syncthreads();
    float* xt = g_xt + (size_t)b * 512u * 8192u;
#pragma unroll
    for (int i = ty; i < 32; i += 8)
        xt[(size_t)(d0 + i) * 8192u + n0 + tx] = tile[tx][i];
}

__global__ void k_tout(float* __restrict__ out) {
    __shared__ float tile[32][33];
    int b = blockIdx.z;
    int d0 = blockIdx.x << 5, n0 = blockIdx.y << 5;
    int tx = threadIdx.x, ty = threadIdx.y;
    const float* yt = g_yt + (size_t)b * 512u * 8192u;
#pragma unroll
    for (int i = ty; i < 32; i += 8)
        tile[i][tx] = yt[(size_t)(d0 + i) * 8192u + n0 + tx];
    __syncthreads();
#pragma unroll
    for (int i = ty; i < 32; i += 8)
        out[((size_t)b * 8192u + n0 + i) * 512u + d0 + tx] = tile[tx][i];
}

// Per-channel: interp coeffs -> a[k] -> irfft -> analytic window -> rfft -> g_spec
__global__ void __launch_bounds__(512, 2) k_filter(const float* __restrict__ coeffs,
                                                   const float* __restrict__ dc) {
    extern __shared__ float2 sm[];
    float2* buf = sm;                       // 8704
    float2* T   = sm + 8704;                // 1024
    float*  cf  = (float*)(sm + 9728);      // 512 floats
    int d = blockIdx.x;
    int tid = threadIdx.x;
    for (int j = tid; j < 1024; j += 512) T[j] = g_tw[j];
    cf[tid] = coeffs[d * 512 + tid];
    float dcv = dc[d];
    __syncthreads();

    auto interp = [&](int k) -> float {
        if (k == 0) return dcv;
        float src = ((float)k - 0.5f) * 0.0625f - 0.5f;
        src = fminf(fmaxf(src, 0.0f), 511.0f);
        int lo = (int)src;
        int hi = min(lo + 1, 511);
        float w = src - (float)lo;
        float clo = cf[lo];
        return fmaf(cf[hi] - clo, w, clo);
    };

    // Build Z (freq domain, coefficient k at digit-rev position) for inverse FFT
    for (int k = tid; k < 8192; k += 512) {
        float ak  = interp(k);
        float akk = interp(8192 - k);
        float fe = 0.5f * (ak + akk);
        float g  = 0.5f * (ak - akk);
        float2 t2 = tw16384(T, k);
        buf[IDX(drev(k))] = make_float2(fmaf(t2.y, g, fe), t2.x * g);
    }
    fft_inv(buf, T);                         // digit-rev in -> natural out (x8192)

    const float inv = 1.0f / 8192.0f;
    for (int j = tid; j < 8192; j += 512) {
        float2 z = buf[IDX(j)];
        float sx, sy;
        if (j == 0)         { sx = inv;        sy = 2.0f * inv; }
        else if (j < 4096)  { sx = 2.0f * inv; sy = 2.0f * inv; }
        else if (j == 4096) { sx = inv;        sy = 0.0f; }
        else                { sx = 0.0f;       sy = 0.0f; }
        buf[IDX(j)] = make_float2(z.x * sx, z.y * sy);
    }
    fft_fwd(buf, T);                         // natural in -> digit-rev out

    float2* sp = g_spec + (size_t)d * 8200u;
    for (int k = tid + 1; k <= 4095; k += 512) {
        float2 P = buf[IDX(drev(k))], Q = buf[IDX(drev(8192 - k))];
        float2 Fe = make_float2(0.5f * (P.x + Q.x), 0.5f * (P.y - Q.y));
        float2 Dd = make_float2(P.x - Q.x, P.y + Q.y);
        float2 Fo = make_float2(0.5f * Dd.y, -0.5f * Dd.x);
        float2 t2 = tw16384(T, k);
        float2 Xk = cadd(Fe, cmul(t2, Fo));
        float2 nt = make_float2(-t2.x, t2.y);
        float2 Xkk = cadd(make_float2(Fe.x, -Fe.y), cmul(nt, make_float2(Fo.x, -Fo.y)));
        sp[k] = Xk;
        sp[8192 - k] = Xkk;
    }
    if (tid == 0) {
        float2 Z0 = buf[IDX(0)];
        sp[0]    = make_float2(Z0.x + Z0.y, 0.0f);
        sp[8192] = make_float2(Z0.x - Z0.y, 0.0f);
        float2 Z4 = buf[IDX(1)];             // drev(4096) = 1
        sp[4096] = make_float2(Z4.x, -Z4.y);
    }
}

// Per (b,d): rfft(x row) * spec -> irfft -> first 8192 samples
__global__ void __launch_bounds__(512, 2) k_conv() {
    extern __shared__ float2 sm[];
    float2* buf = sm;                       // 8704
    float2* T   = sm + 8704;                // 1024
    int bid = blockIdx.x;
    int d = bid & 511;
    int b = bid >> 9;
    int tid = threadIdx.x;
    for (int j = tid; j < 1024; j += 512) T[j] = g_tw[j];
    const float2* xr = (const float2*)(g_xt + ((size_t)(b * 512 + d) << 13));
    for (int j = tid; j < 4096; j += 512) buf[IDX(j)] = xr[j];
    for (int j = 4096 + tid; j < 8192; j += 512) buf[IDX(j)] = make_float2(0.f, 0.f);
    fft_fwd(buf, T);                         // natural in -> digit-rev out

    const float2* sp = g_spec + (size_t)d * 8200u;
    for (int k = tid + 1; k <= 4095; k += 512) {
        int kk = 8192 - k;
        int p1 = IDX(drev(k)), p2 = IDX(drev(kk));
        float2 P = buf[p1], Q = buf[p2];
        float2 Fe = make_float2(0.5f * (P.x + Q.x), 0.5f * (P.y - Q.y));
        float2 Dd = make_float2(P.x - Q.x, P.y + Q.y);
        float2 Fo = make_float2(0.5f * Dd.y, -0.5f * Dd.x);
        float2 t2 = tw16384(T, k);
        float2 Xk = cadd(Fe, cmul(t2, Fo));
        float2 nt = make_float2(-t2.x, t2.y);
        float2 Xkk = cadd(make_float2(Fe.x, -Fe.y), cmul(nt, make_float2(Fo.x, -Fo.y)));
        float2 Yk  = cmul(Xk,  sp[k]);
        float2 Ykk = cmul(Xkk, sp[kk]);
        float2 Fe2 = make_float2(0.5f * (Yk.x + Ykk.x), 0.5f * (Yk.y - Ykk.y));
        float2 hd  = make_float2(0.5f * (Yk.x - Ykk.x), 0.5f * (Yk.y + Ykk.y));
        float2 ct2 = make_float2(t2.x, -t2.y);
        float2 Fo2 = cmul(ct2, hd);
        buf[p1] = make_float2(Fe2.x - Fo2.y,  Fe2.y + Fo2.x);
        buf[p2] = make_float2(Fe2.x + Fo2.y, -Fe2.y + Fo2.x);
    }
    if (tid == 0) {
        float2 Z0 = buf[IDX(0)];
        float X0 = Z0.x + Z0.y;
        float XN = Z0.x - Z0.y;
        float Y0 = X0 * sp[0].x;
        float YN = XN * sp[8192].x;
        buf[IDX(0)] = make_float2(0.5f * (Y0 + YN), 0.5f * (Y0 - YN));
        float2 Z4 = buf[IDX(1)];             // drev(4096) = 1
        float2 X4 = make_float2(Z4.x, -Z4.y);
        float2 Y4 = cmul(X4, sp[4096]);
        buf[IDX(1)] = make_float2(Y4.x, -Y4.y);
    }
    fft_inv(buf, T);                         // digit-rev in -> natural out

    const float inv = 1.0f / 8192.0f;
    float2* yr = (float2*)(g_yt + ((size_t)(b * 512 + d) << 13));
    for (int j = tid; j < 4096; j += 512) {
        float2 w = buf[IDX(j)];
        yr[j] = make_float2(w.x * inv, w.y * inv);
    }
}

// ---------------------------------------------------------------------------

extern "C" void kernel_launch(void* const* d_in, const int* in_sizes, int n_in,
                              void* d_out, int out_size) {
    const float* x      = (const float*)d_in[0];
    const float* coeffs = (const float*)d_in[1];
    const float* dc     = (const float*)d_in[2];
    float* out = (float*)d_out;

    size_t smem_c = 9728u * sizeof(float2);            // 77824
    size_t smem_f = smem_c + 512u * sizeof(float);     // 79872
    cudaFuncSetAttribute(k_filter, cudaFuncAttributeMaxDynamicSharedMemorySize, (int)smem_f);
    cudaFuncSetAttribute(k_conv,   cudaFuncAttributeMaxDynamicSharedMemorySize, (int)smem_c);

    k_tw<<<2, 512>>>();
    k_tin<<<dim3(16, 256, 8), dim3(32, 8)>>>(x);
    k_filter<<<512, 512, smem_f>>>(coeffs, dc);
    k_conv<<<4096, 512, smem_c>>>();
    k_tout<<<dim3(16, 256, 8), dim3(32, 8)>>>(out);
}